// round 13
// baseline (speedup 1.0000x reference)
#include <cuda_runtime.h>
#include <cuda_fp16.h>
#include <cstdint>

// ---------------- problem constants ----------------
#define Bn    128
#define Hn    12
#define Nn    100
#define NPH   104            // padded G row pitch in halfs (208B rows, 16B aligned)
#define HPC   4              // heads per CTA
#define CL    3              // CTAs per cluster (HPC*CL == Hn)
#define WPH   2              // warps per head
#define NW    (HPC*WPH)      // 8 warps per CTA
#define NT    (NW*32)        // 256 threads
#define ITERS 500

#define GAMMA_ 5.0f
#define COST_  1e-3f
#define KAPPA_ 2.0627128075074256f
#define PEN_   100.0f
#define LR_    0.01f

// SMEM layout (bytes)
#define G_BYTES    (HPC*Nn*NPH*2)              // 83200
#define WBUF_BYTE  G_BYTES                     // fp32 w: [2][HPC][128] = 4096 B
#define PA_BYTE    (WBUF_BYTE + 2*HPC*128*4)   // partial-a: [NW][128] f32
#define SMEM_BYTES (PA_BYTE + NW*128*4)        // 91392 B -> 2 CTAs/SM

// Scratch for G = L L^T per (b,h) in fp16 (~32 MB)
__device__ __half g_G[(size_t)Bn * Hn * Nn * NPH];

// ---------------------------------------------------------------------------
// Precompute G[b,h] = L L^T (fp32 accumulate, fp16 store)
// ---------------------------------------------------------------------------
__global__ __launch_bounds__(256) void precompute_G(const float* __restrict__ L) {
    __shared__ __align__(16) float Ls[Nn * Nn];
    const int bh = blockIdx.x;
    const float4* src = (const float4*)(L + (size_t)bh * Nn * Nn);
    float4* d4 = (float4*)Ls;
    for (int i = threadIdx.x; i < Nn * Nn / 4; i += blockDim.x) d4[i] = src[i];
    __syncthreads();
    __half* outp = g_G + (size_t)bh * Nn * NPH;
    for (int idx = threadIdx.x; idx < Nn * NPH; idx += blockDim.x) {
        const int n = idx / NPH;
        const int j = idx - n * NPH;
        float r = 0.0f;
        if (j < Nn) {
            const float4* ra = (const float4*)(Ls + n * Nn);
            const float4* rb = (const float4*)(Ls + j * Nn);
            float a0 = 0.f, a1 = 0.f, a2 = 0.f, a3 = 0.f;
#pragma unroll
            for (int m = 0; m < Nn / 4; m++) {
                float4 x = ra[m], y = rb[m];
                a0 = fmaf(x.x, y.x, a0);
                a1 = fmaf(x.y, y.y, a1);
                a2 = fmaf(x.z, y.z, a2);
                a3 = fmaf(x.w, y.w, a3);
            }
            r = (a0 + a1) + (a2 + a3);
        }
        outp[idx] = __float2half_rn(r);
    }
}

// ---------------------------------------------------------------------------
// Helpers
// ---------------------------------------------------------------------------
__device__ __forceinline__ float red1(float x) {
#pragma unroll
    for (int o = 16; o; o >>= 1) x += __shfl_xor_sync(0xffffffffu, x, o);
    return x;
}

__device__ __forceinline__ void red2(float& x, float& y) {
#pragma unroll
    for (int o = 16; o; o >>= 1) {
        x += __shfl_xor_sync(0xffffffffu, x, o);
        y += __shfl_xor_sync(0xffffffffu, y, o);
    }
}

#define CLUSTER_SYNC_() \
    asm volatile("barrier.cluster.arrive.aligned;\n\tbarrier.cluster.wait.aligned;" ::: "memory")

#define PAIR_BAR_(id) \
    asm volatile("bar.sync %0, 64;" :: "r"(id) : "memory")

// ---------------------------------------------------------------------------
// Solver: cluster of 3 CTAs per batch; CTA rank r owns heads 4r..4r+3,
// two warps per head (matvec split over j). Epilogue runs only on the
// half==0 warp; Michelot counts via ballots.
// G fp16 in SMEM; matvec math in fp32 (bit-identical to R10).
// ---------------------------------------------------------------------------
__global__ __cluster_dims__(CL, 1, 1) __launch_bounds__(NT, 2)
void solve_kernel(const float* __restrict__ mu, const float* __restrict__ wprev,
                  const float* __restrict__ lim, float* __restrict__ out)
{
    extern __shared__ __align__(16) char smraw[];
    __half* Gs  = (__half*)smraw;                 // [HPC][Nn][NPH] fp16
    float* wbuf = (float*)(smraw + WBUF_BYTE);    // [2][HPC][128] fp32
    float* pa   = (float*)(smraw + PA_BYTE);      // [NW][128] partial-a

    const int tid  = threadIdx.x;
    const int lane = tid & 31;
    const int warp = tid >> 5;            // 0..7
    const int head = warp & (HPC - 1);    // head within CTA
    const int half = warp >> 2;           // 0: j in [0,52), 1: j in [52,100)
    uint32_t rank;
    asm("mov.u32 %0, %%cluster_ctarank;" : "=r"(rank));
    const int  b   = blockIdx.x / CL;
    const int  h   = HPC * (int)rank + head;
    const int  bh  = b * Hn + h;
    const bool vlane = (lane < 25);       // 25 lanes x 4 elems = 100
    const int  lv  = vlane ? lane : 24;   // clamped lane for safe addresses

    // Load this CTA's 4 fp16 G matrices into SMEM
    {
        const uint4* s4 = (const uint4*)(g_G + (size_t)(b * Hn + HPC * (int)rank) * Nn * NPH);
        uint4* d4 = (uint4*)Gs;
        const int n4 = G_BYTES / 16;
        for (int i = tid; i < n4; i += NT) d4[i] = s4[i];
    }
    // Init both w buffers, zero pads
    for (int i = tid; i < 2 * HPC * 128; i += NT) {
        int e = i & 127;
        wbuf[i] = (e < Nn) ? wprev[(size_t)b * Nn + e] : 0.0f;
    }

    // Per-lane registers
    float4 mu4, w4, wlag0;
    {
        const float4* mp = (const float4*)(mu + (size_t)bh * Nn);
        const float4* pp = (const float4*)(wprev + (size_t)b * Nn);
        float4 m = mp[lv], p = pp[lv];
        if (!vlane) { m = make_float4(0, 0, 0, 0); p = make_float4(0, 0, 0, 0); }
        mu4 = m; w4 = p; wlag0 = p;       // constant lag for h==0
    }
    const float limb    = lim[b];
    const bool  h_first = (h == 0);
    const bool  h_last  = (h == Hn - 1);
    const float fnext   = h_last ? 0.0f : 1.0f;

    // DSMEM addresses for boundary-head neighbor reads (per buffer)
    uint32_t ra_lag[2], ra_next[2];
    {
        uint32_t wbase = (uint32_t)__cvta_generic_to_shared(wbuf);
        uint32_t rlo = (rank > 0) ? (rank - 1) : 0u;
        uint32_t rhi = (rank + 1 < CL) ? (rank + 1) : rank;
#pragma unroll
        for (int bu = 0; bu < 2; bu++) {
            uint32_t off_lag  = wbase + (uint32_t)(((bu * HPC + (HPC - 1)) * 128 + 4 * lv) * 4);
            uint32_t off_next = wbase + (uint32_t)(((bu * HPC + 0) * 128 + 4 * lv) * 4);
            asm("mapa.shared::cluster.u32 %0, %1, %2;" : "=r"(ra_lag[bu])  : "r"(off_lag),  "r"(rlo));
            asm("mapa.shared::cluster.u32 %0, %1, %2;" : "=r"(ra_next[bu]) : "r"(off_next), "r"(rhi));
        }
    }

    CLUSTER_SYNC_();   // publish G + initial w to whole cluster

    const __half* Gh = Gs + head * (Nn * NPH) + 4 * lv;   // lane's 4-elem slab
    float* paw       = pa + warp * 128;                   // own partial slot
    const float* pao = pa + (warp ^ 4) * 128 + 4 * lv;    // pair's partial slot
    const int j0 = half ? 52 : 0;
    const int j1 = half ? 100 : 52;
    const int barid = 1 + head;

    for (int it = 0; it < ITERS; it++) {
        const int cur = it & 1;
        const float* wc = wbuf + (cur * HPC + head) * 128;   // head's current w

        // --- neighbor reads (epilogue warp only; issued before matvec) ---
        float4 wlag4, wnext4;
        if (half == 0) {
            if (h_first) {
                wlag4 = wlag0;
            } else if (head > 0) {
                wlag4 = *(const float4*)(wbuf + (cur * HPC + head - 1) * 128 + 4 * lv);
            } else {
                asm volatile("ld.shared::cluster.v4.f32 {%0,%1,%2,%3}, [%4];"
                             : "=f"(wlag4.x), "=f"(wlag4.y), "=f"(wlag4.z), "=f"(wlag4.w)
                             : "r"(ra_lag[cur]));
            }
            if (h_last) {
                wnext4 = make_float4(0, 0, 0, 0);
            } else if (head < HPC - 1) {
                wnext4 = *(const float4*)(wbuf + (cur * HPC + head + 1) * 128 + 4 * lv);
            } else {
                asm volatile("ld.shared::cluster.v4.f32 {%0,%1,%2,%3}, [%4];"
                             : "=f"(wnext4.x), "=f"(wnext4.y), "=f"(wnext4.z), "=f"(wnext4.w)
                             : "r"(ra_next[cur]));
            }
        }

        // --- partial a = G w over this warp's j-range (fp16 G, fp32 math) ---
        float4 aA = make_float4(0, 0, 0, 0);
        float4 aB = make_float4(0, 0, 0, 0);
#define ROWF4(J) ({                                                            \
            __half2 _p = *(const __half2*)(Gh + (size_t)(J) * NPH);            \
            __half2 _q = *(const __half2*)(Gh + (size_t)(J) * NPH + 2);        \
            float2 _a = __half22float2(_p);                                    \
            float2 _b = __half22float2(_q);                                    \
            make_float4(_a.x, _a.y, _b.x, _b.y); })
#define BLK4(J, ACC) do {                                                      \
            float4 wv = *(const float4*)(wc + (J));                            \
            float4 g0 = ROWF4((J) + 0);                                        \
            float4 g1 = ROWF4((J) + 1);                                        \
            float4 g2 = ROWF4((J) + 2);                                        \
            float4 g3 = ROWF4((J) + 3);                                        \
            ACC.x = fmaf(g0.x, wv.x, ACC.x); ACC.y = fmaf(g0.y, wv.x, ACC.y);  \
            ACC.z = fmaf(g0.z, wv.x, ACC.z); ACC.w = fmaf(g0.w, wv.x, ACC.w);  \
            ACC.x = fmaf(g1.x, wv.y, ACC.x); ACC.y = fmaf(g1.y, wv.y, ACC.y);  \
            ACC.z = fmaf(g1.z, wv.y, ACC.z); ACC.w = fmaf(g1.w, wv.y, ACC.w);  \
            ACC.x = fmaf(g2.x, wv.z, ACC.x); ACC.y = fmaf(g2.y, wv.z, ACC.y);  \
            ACC.z = fmaf(g2.z, wv.z, ACC.z); ACC.w = fmaf(g2.w, wv.z, ACC.w);  \
            ACC.x = fmaf(g3.x, wv.w, ACC.x); ACC.y = fmaf(g3.y, wv.w, ACC.y);  \
            ACC.z = fmaf(g3.z, wv.w, ACC.z); ACC.w = fmaf(g3.w, wv.w, ACC.w);  \
        } while (0)
        int j = j0;
#pragma unroll 3
        for (; j + 8 <= j1; j += 8) {
            BLK4(j, aA);
            BLK4(j + 4, aB);
        }
        if (j < j1) BLK4(j, aA);
#undef BLK4
#undef ROWF4
        aA.x += aB.x; aA.y += aB.y; aA.z += aB.z; aA.w += aB.w;

        // --- combine halves through SMEM scratch (per-head named barrier) ---
        if (vlane) *(float4*)(paw + 4 * lane) = aA;
        PAIR_BAR_(barid);

        if (half == 0) {
            float4 oth = *(const float4*)pao;
            float4 a4;
            a4.x = aA.x + oth.x; a4.y = aA.y + oth.y;
            a4.z = aA.z + oth.z; a4.w = aA.w + oth.w;

            // --- scalars: ret = mu.w, sig2 = w.Gw ---
            float r0 = mu4.x * w4.x + mu4.y * w4.y + mu4.z * w4.z + mu4.w * w4.w;
            float r1 = w4.x * a4.x + w4.y * a4.y + w4.z * a4.z + w4.w * a4.w;
            red2(r0, r1);
            const float s2      = r1 + 1e-12f;
            const float inv_sig = rsqrtf(s2);
            const float sigma   = s2 * inv_sig;
            const float zv      = KAPPA_ * sigma - r0 - limb;
            const float pen     = (zv > 0.0f) ? PEN_ : 0.0f;
            const float ca      = 2.0f * GAMMA_ + pen * KAPPA_ * inv_sig;
            const float cm      = -(1.0f + pen);

            // --- gradient + step: v = w - LR * g ---
            float4 v;
            {
                float d, t;
                t = cm * mu4.x + ca * a4.x;
                d = w4.x - wlag4.x;  t += COST_ * d * rsqrtf(fmaf(d, d, 1e-10f));
                d = wnext4.x - w4.x; t -= fnext * COST_ * d * rsqrtf(fmaf(d, d, 1e-10f));
                v.x = w4.x - LR_ * t;
                t = cm * mu4.y + ca * a4.y;
                d = w4.y - wlag4.y;  t += COST_ * d * rsqrtf(fmaf(d, d, 1e-10f));
                d = wnext4.y - w4.y; t -= fnext * COST_ * d * rsqrtf(fmaf(d, d, 1e-10f));
                v.y = w4.y - LR_ * t;
                t = cm * mu4.z + ca * a4.z;
                d = w4.z - wlag4.z;  t += COST_ * d * rsqrtf(fmaf(d, d, 1e-10f));
                d = wnext4.z - w4.z; t -= fnext * COST_ * d * rsqrtf(fmaf(d, d, 1e-10f));
                v.z = w4.z - LR_ * t;
                t = cm * mu4.w + ca * a4.w;
                d = w4.w - wlag4.w;  t += COST_ * d * rsqrtf(fmaf(d, d, 1e-10f));
                d = wnext4.w - w4.w; t -= fnext * COST_ * d * rsqrtf(fmaf(d, d, 1e-10f));
                v.w = w4.w - LR_ * t;
            }
            if (!vlane) v = make_float4(-1e30f, -1e30f, -1e30f, -1e30f);

            // --- exact simplex projection (Michelot; ballot counts) ---
            float s0 = red1(vlane ? (v.x + v.y + v.z + v.w) : 0.0f);
            int   kk    = 100;
            float theta = (s0 - 1.0f) * 0.01f;
#pragma unroll 1
            for (int pass = 0; pass < 50; pass++) {
                bool c0 = v.x > theta, c1 = v.y > theta;
                bool c2 = v.z > theta, c3 = v.w > theta;
                float bs = (c0 ? v.x : 0.0f) + (c1 ? v.y : 0.0f)
                         + (c2 ? v.z : 0.0f) + (c3 ? v.w : 0.0f);
                unsigned m0 = __ballot_sync(0xffffffffu, c0);
                unsigned m1 = __ballot_sync(0xffffffffu, c1);
                unsigned m2 = __ballot_sync(0xffffffffu, c2);
                unsigned m3 = __ballot_sync(0xffffffffu, c3);
                int bk = __popc(m0) + __popc(m1) + __popc(m2) + __popc(m3);
                bs = red1(bs);
                if (bk == kk) break;
                kk = bk;
                theta = (bs - 1.0f) / (float)bk;
            }
            w4.x = fmaxf(v.x - theta, 0.0f);
            w4.y = fmaxf(v.y - theta, 0.0f);
            w4.z = fmaxf(v.z - theta, 0.0f);
            w4.w = fmaxf(v.w - theta, 0.0f);

            // --- publish new w (double buffer) ---
            if (vlane)
                *(float4*)(wbuf + ((cur ^ 1) * HPC + head) * 128 + 4 * lane) = w4;
        }
        CLUSTER_SYNC_();
    }

    if (half == 0 && vlane)
        *(float4*)(out + (size_t)bh * Nn + 4 * lane) = w4;
}

// ---------------------------------------------------------------------------
// Launch
// ---------------------------------------------------------------------------
extern "C" void kernel_launch(void* const* d_in, const int* in_sizes, int n_in,
                              void* d_out, int out_size) {
    const float *mu = nullptr, *L = nullptr, *wprev = nullptr, *lim = nullptr;
    for (int i = 0; i < n_in; i++) {
        switch (in_sizes[i]) {
            case Bn * Hn * Nn:       mu    = (const float*)d_in[i]; break;
            case Bn * Hn * Nn * Nn:  L     = (const float*)d_in[i]; break;
            case Bn * Nn:            wprev = (const float*)d_in[i]; break;
            case Bn:                 lim   = (const float*)d_in[i]; break;
            default: break;
        }
    }
    float* out = (float*)d_out;

    cudaFuncSetAttribute(solve_kernel, cudaFuncAttributeMaxDynamicSharedMemorySize, SMEM_BYTES);

    precompute_G<<<Bn * Hn, 256>>>(L);
    solve_kernel<<<Bn * CL, NT, SMEM_BYTES>>>(mu, wprev, lim, out);
}

// round 14
// speedup vs baseline: 1.4872x; 1.4872x over previous
#include <cuda_runtime.h>
#include <cuda_fp16.h>
#include <cstdint>

// ---------------- problem constants ----------------
#define Bn    128
#define Hn    12
#define Nn    100
#define NPH   104            // padded G row pitch in halfs (208B rows, 16B aligned)
#define HPC   4              // heads per CTA
#define CL    3              // CTAs per cluster (HPC*CL == Hn)
#define WPH   2              // warps per head
#define NW    (HPC*WPH)      // 8 warps per CTA
#define NT    (NW*32)        // 256 threads
#define ITERS 500

#define GAMMA_ 5.0f
#define COST_  1e-3f
#define KAPPA_ 2.0627128075074256f
#define PEN_   100.0f
#define LR_    0.01f

// SMEM layout (bytes)
#define G_BYTES    (HPC*Nn*NPH*2)              // 83200
#define WBUF_BYTE  G_BYTES                     // fp32 w: [2][HPC][128] = 4096 B
#define PA_BYTE    (WBUF_BYTE + 2*HPC*128*4)   // partial-a: [NW][128] f32
#define MB_BYTE    (PA_BYTE + NW*128*4)        // 2 mbarriers (16 B)
#define SMEM_BYTES (MB_BYTE + 16)              // 91408 B -> 2 CTAs/SM

// Scratch for G = L L^T per (b,h) in fp16 (~32 MB)
__device__ __half g_G[(size_t)Bn * Hn * Nn * NPH];

// ---------------------------------------------------------------------------
// Precompute G[b,h] = L L^T (fp32 accumulate, fp16 store)
// ---------------------------------------------------------------------------
__global__ __launch_bounds__(256) void precompute_G(const float* __restrict__ L) {
    __shared__ __align__(16) float Ls[Nn * Nn];
    const int bh = blockIdx.x;
    const float4* src = (const float4*)(L + (size_t)bh * Nn * Nn);
    float4* d4 = (float4*)Ls;
    for (int i = threadIdx.x; i < Nn * Nn / 4; i += blockDim.x) d4[i] = src[i];
    __syncthreads();
    __half* outp = g_G + (size_t)bh * Nn * NPH;
    for (int idx = threadIdx.x; idx < Nn * NPH; idx += blockDim.x) {
        const int n = idx / NPH;
        const int j = idx - n * NPH;
        float r = 0.0f;
        if (j < Nn) {
            const float4* ra = (const float4*)(Ls + n * Nn);
            const float4* rb = (const float4*)(Ls + j * Nn);
            float a0 = 0.f, a1 = 0.f, a2 = 0.f, a3 = 0.f;
#pragma unroll
            for (int m = 0; m < Nn / 4; m++) {
                float4 x = ra[m], y = rb[m];
                a0 = fmaf(x.x, y.x, a0);
                a1 = fmaf(x.y, y.y, a1);
                a2 = fmaf(x.z, y.z, a2);
                a3 = fmaf(x.w, y.w, a3);
            }
            r = (a0 + a1) + (a2 + a3);
        }
        outp[idx] = __float2half_rn(r);
    }
}

// ---------------------------------------------------------------------------
// Helpers
// ---------------------------------------------------------------------------
__device__ __forceinline__ float red1(float x) {
#pragma unroll
    for (int o = 16; o; o >>= 1) x += __shfl_xor_sync(0xffffffffu, x, o);
    return x;
}

__device__ __forceinline__ void red2(float& x, float& y) {
#pragma unroll
    for (int o = 16; o; o >>= 1) {
        x += __shfl_xor_sync(0xffffffffu, x, o);
        y += __shfl_xor_sync(0xffffffffu, y, o);
    }
}

#define CLUSTER_SYNC_() \
    asm volatile("barrier.cluster.arrive.aligned;\n\tbarrier.cluster.wait.aligned;" ::: "memory")

#define PAIR_BAR_(id) \
    asm volatile("bar.sync %0, 64;" :: "r"(id) : "memory")

// Wait on local mbarrier with given phase parity, acquire at cluster scope.
__device__ __forceinline__ void mbar_wait_cluster(uint32_t addr, uint32_t par) {
    asm volatile(
        "{\n\t.reg .pred P;\n\t"
        "WAITL_%=:\n\t"
        "mbarrier.try_wait.parity.acquire.cluster.shared::cta.b64 P, [%0], %1, 0x989680;\n\t"
        "@P bra.uni WD_%=;\n\t"
        "bra.uni WAITL_%=;\n\t"
        "WD_%=:\n\t}"
        :: "r"(addr), "r"(par) : "memory");
}

// Arrive on a (mapa-resolved) remote CTA mbarrier, release at cluster scope.
__device__ __forceinline__ void mbar_arrive_remote(uint32_t remote_addr) {
    asm volatile(
        "mbarrier.arrive.release.cluster.shared::cluster.b64 _, [%0];"
        :: "r"(remote_addr) : "memory");
}

// ---------------------------------------------------------------------------
// Solver: cluster of 3 CTAs per batch; CTA rank r owns heads 4r..4r+3,
// two warps per head. G fp16 in SMEM; fp32 math (identical to the 2629us
// R10 kernel). Per-iteration cross-CTA sync via neighbor mbarrier
// handshakes instead of a full cluster barrier.
// ---------------------------------------------------------------------------
__global__ __cluster_dims__(CL, 1, 1) __launch_bounds__(NT, 2)
void solve_kernel(const float* __restrict__ mu, const float* __restrict__ wprev,
                  const float* __restrict__ lim, float* __restrict__ out)
{
    extern __shared__ __align__(16) char smraw[];
    __half* Gs  = (__half*)smraw;                 // [HPC][Nn][NPH] fp16
    float* wbuf = (float*)(smraw + WBUF_BYTE);    // [2][HPC][128] fp32
    float* pa   = (float*)(smraw + PA_BYTE);      // [NW][128] partial-a

    const int tid  = threadIdx.x;
    const int lane = tid & 31;
    const int warp = tid >> 5;            // 0..7
    const int head = warp & (HPC - 1);    // head within CTA
    const int half = warp >> 2;           // 0: j in [0,52), 1: j in [52,100)
    uint32_t rank;
    asm("mov.u32 %0, %%cluster_ctarank;" : "=r"(rank));
    const int  b   = blockIdx.x / CL;
    const int  h   = HPC * (int)rank + head;
    const int  bh  = b * Hn + h;
    const bool vlane = (lane < 25);       // 25 lanes x 4 elems = 100
    const int  lv  = vlane ? lane : 24;   // clamped lane for safe addresses

    const uint32_t smem_u32 = (uint32_t)__cvta_generic_to_shared(smraw);
    const uint32_t mb0 = smem_u32 + MB_BYTE;      // full[0]
    const uint32_t mb1 = mb0 + 8;                 // full[1]
    const bool has_lo = (rank > 0);
    const bool has_hi = (rank + 1 < CL);

    // Load this CTA's 4 fp16 G matrices into SMEM
    {
        const uint4* s4 = (const uint4*)(g_G + (size_t)(b * Hn + HPC * (int)rank) * Nn * NPH);
        uint4* d4 = (uint4*)Gs;
        const int n4 = G_BYTES / 16;
        for (int i = tid; i < n4; i += NT) d4[i] = s4[i];
    }
    // Init both w buffers, zero pads
    for (int i = tid; i < 2 * HPC * 128; i += NT) {
        int e = i & 127;
        wbuf[i] = (e < Nn) ? wprev[(size_t)b * Nn + e] : 0.0f;
    }
    // Init neighbor-handshake mbarriers (count = number of neighbors)
    if (tid == 0) {
        const uint32_t n_nb = (uint32_t)((has_lo ? 1 : 0) + (has_hi ? 1 : 0));
        asm volatile("mbarrier.init.shared.b64 [%0], %1;" :: "r"(mb0), "r"(n_nb) : "memory");
        asm volatile("mbarrier.init.shared.b64 [%0], %1;" :: "r"(mb1), "r"(n_nb) : "memory");
    }

    // Per-lane registers
    float4 mu4, w4, wlag0;
    {
        const float4* mp = (const float4*)(mu + (size_t)bh * Nn);
        const float4* pp = (const float4*)(wprev + (size_t)b * Nn);
        float4 m = mp[lv], p = pp[lv];
        if (!vlane) { m = make_float4(0, 0, 0, 0); p = make_float4(0, 0, 0, 0); }
        mu4 = m; w4 = p; wlag0 = p;       // constant lag for h==0
    }
    const float limb    = lim[b];
    const bool  h_first = (h == 0);
    const bool  h_last  = (h == Hn - 1);
    const float fnext   = h_last ? 0.0f : 1.0f;
    // This warp performs cross-CTA reads -> must wait on the handshake
    const bool remote_rd = (head == 0 && has_lo) || (head == HPC - 1 && has_hi);

    // DSMEM addresses for boundary-head neighbor reads (per buffer) and
    // for remote arrivals on neighbors' full[] barriers.
    uint32_t ra_lag[2], ra_next[2];
    uint32_t arr_lo0 = 0, arr_lo1 = 0, arr_hi0 = 0, arr_hi1 = 0;
    {
        uint32_t wbase = (uint32_t)__cvta_generic_to_shared(wbuf);
        uint32_t rlo = has_lo ? (rank - 1) : 0u;
        uint32_t rhi = has_hi ? (rank + 1) : rank;
#pragma unroll
        for (int bu = 0; bu < 2; bu++) {
            uint32_t off_lag  = wbase + (uint32_t)(((bu * HPC + (HPC - 1)) * 128 + 4 * lv) * 4);
            uint32_t off_next = wbase + (uint32_t)(((bu * HPC + 0) * 128 + 4 * lv) * 4);
            asm("mapa.shared::cluster.u32 %0, %1, %2;" : "=r"(ra_lag[bu])  : "r"(off_lag),  "r"(rlo));
            asm("mapa.shared::cluster.u32 %0, %1, %2;" : "=r"(ra_next[bu]) : "r"(off_next), "r"(rhi));
        }
        asm("mapa.shared::cluster.u32 %0, %1, %2;" : "=r"(arr_lo0) : "r"(mb0), "r"(rlo));
        asm("mapa.shared::cluster.u32 %0, %1, %2;" : "=r"(arr_lo1) : "r"(mb1), "r"(rlo));
        asm("mapa.shared::cluster.u32 %0, %1, %2;" : "=r"(arr_hi0) : "r"(mb0), "r"(rhi));
        asm("mapa.shared::cluster.u32 %0, %1, %2;" : "=r"(arr_hi1) : "r"(mb1), "r"(rhi));
    }

    CLUSTER_SYNC_();   // publish G + initial w + mbarrier init to whole cluster

    const __half* Gh = Gs + head * (Nn * NPH) + 4 * lv;   // lane's 4-elem slab
    float* paw       = pa + warp * 128;                   // own partial slot
    const float* pao = pa + (warp ^ 4) * 128 + 4 * lv;    // pair's partial slot
    const int j0 = half ? 52 : 0;
    const int j1 = half ? 100 : 52;
    const int barid = 1 + head;

    for (int it = 0; it < ITERS; it++) {
        const int cur = it & 1;
        const float* wc = wbuf + (cur * HPC + head) * 128;   // head's current w

        // --- handshake: remote-reading warps wait for neighbor publish ---
        if (it > 0 && remote_rd) {
            mbar_wait_cluster(cur ? mb1 : mb0, (uint32_t)(((it - 1) >> 1) & 1));
        }

        // --- neighbor reads (issued early; latency hidden by matvec) ---
        float4 wlag4, wnext4;
        if (h_first) {
            wlag4 = wlag0;
        } else if (head > 0) {
            wlag4 = *(const float4*)(wbuf + (cur * HPC + head - 1) * 128 + 4 * lv);
        } else {
            asm volatile("ld.shared::cluster.v4.f32 {%0,%1,%2,%3}, [%4];"
                         : "=f"(wlag4.x), "=f"(wlag4.y), "=f"(wlag4.z), "=f"(wlag4.w)
                         : "r"(ra_lag[cur]));
        }
        if (h_last) {
            wnext4 = make_float4(0, 0, 0, 0);
        } else if (head < HPC - 1) {
            wnext4 = *(const float4*)(wbuf + (cur * HPC + head + 1) * 128 + 4 * lv);
        } else {
            asm volatile("ld.shared::cluster.v4.f32 {%0,%1,%2,%3}, [%4];"
                         : "=f"(wnext4.x), "=f"(wnext4.y), "=f"(wnext4.z), "=f"(wnext4.w)
                         : "r"(ra_next[cur]));
        }

        // --- partial a = G w over this warp's j-range (fp16 G, fp32 math) ---
        float4 aA = make_float4(0, 0, 0, 0);
        float4 aB = make_float4(0, 0, 0, 0);
#define ROWF4(J) ({                                                            \
            __half2 _p = *(const __half2*)(Gh + (size_t)(J) * NPH);            \
            __half2 _q = *(const __half2*)(Gh + (size_t)(J) * NPH + 2);        \
            float2 _a = __half22float2(_p);                                    \
            float2 _b = __half22float2(_q);                                    \
            make_float4(_a.x, _a.y, _b.x, _b.y); })
#define BLK4(J, ACC) do {                                                      \
            float4 wv = *(const float4*)(wc + (J));                            \
            float4 g0 = ROWF4((J) + 0);                                        \
            float4 g1 = ROWF4((J) + 1);                                        \
            float4 g2 = ROWF4((J) + 2);                                        \
            float4 g3 = ROWF4((J) + 3);                                        \
            ACC.x = fmaf(g0.x, wv.x, ACC.x); ACC.y = fmaf(g0.y, wv.x, ACC.y);  \
            ACC.z = fmaf(g0.z, wv.x, ACC.z); ACC.w = fmaf(g0.w, wv.x, ACC.w);  \
            ACC.x = fmaf(g1.x, wv.y, ACC.x); ACC.y = fmaf(g1.y, wv.y, ACC.y);  \
            ACC.z = fmaf(g1.z, wv.y, ACC.z); ACC.w = fmaf(g1.w, wv.y, ACC.w);  \
            ACC.x = fmaf(g2.x, wv.z, ACC.x); ACC.y = fmaf(g2.y, wv.z, ACC.y);  \
            ACC.z = fmaf(g2.z, wv.z, ACC.z); ACC.w = fmaf(g2.w, wv.z, ACC.w);  \
            ACC.x = fmaf(g3.x, wv.w, ACC.x); ACC.y = fmaf(g3.y, wv.w, ACC.y);  \
            ACC.z = fmaf(g3.z, wv.w, ACC.z); ACC.w = fmaf(g3.w, wv.w, ACC.w);  \
        } while (0)
        int j = j0;
#pragma unroll 3
        for (; j + 8 <= j1; j += 8) {
            BLK4(j, aA);
            BLK4(j + 4, aB);
        }
        if (j < j1) BLK4(j, aA);
#undef BLK4
#undef ROWF4
        aA.x += aB.x; aA.y += aB.y; aA.z += aB.z; aA.w += aB.w;

        // --- combine halves through SMEM scratch (per-head named barrier) ---
        if (vlane) *(float4*)(paw + 4 * lane) = aA;
        PAIR_BAR_(barid);
        float4 oth = *(const float4*)pao;
        float4 a4;
        a4.x = aA.x + oth.x; a4.y = aA.y + oth.y;
        a4.z = aA.z + oth.z; a4.w = aA.w + oth.w;

        // --- scalars: ret = mu.w, sig2 = w.Gw (both warps, identical) ---
        float r0 = mu4.x * w4.x + mu4.y * w4.y + mu4.z * w4.z + mu4.w * w4.w;
        float r1 = w4.x * a4.x + w4.y * a4.y + w4.z * a4.z + w4.w * a4.w;
        red2(r0, r1);
        const float s2      = r1 + 1e-12f;
        const float inv_sig = rsqrtf(s2);
        const float sigma   = s2 * inv_sig;
        const float zv      = KAPPA_ * sigma - r0 - limb;
        const float pen     = (zv > 0.0f) ? PEN_ : 0.0f;
        const float ca      = 2.0f * GAMMA_ + pen * KAPPA_ * inv_sig;
        const float cm      = -(1.0f + pen);

        // --- gradient + step: v = w - LR * g ---
        float4 v;
        {
            float d, t;
            t = cm * mu4.x + ca * a4.x;
            d = w4.x - wlag4.x;  t += COST_ * d * rsqrtf(fmaf(d, d, 1e-10f));
            d = wnext4.x - w4.x; t -= fnext * COST_ * d * rsqrtf(fmaf(d, d, 1e-10f));
            v.x = w4.x - LR_ * t;
            t = cm * mu4.y + ca * a4.y;
            d = w4.y - wlag4.y;  t += COST_ * d * rsqrtf(fmaf(d, d, 1e-10f));
            d = wnext4.y - w4.y; t -= fnext * COST_ * d * rsqrtf(fmaf(d, d, 1e-10f));
            v.y = w4.y - LR_ * t;
            t = cm * mu4.z + ca * a4.z;
            d = w4.z - wlag4.z;  t += COST_ * d * rsqrtf(fmaf(d, d, 1e-10f));
            d = wnext4.z - w4.z; t -= fnext * COST_ * d * rsqrtf(fmaf(d, d, 1e-10f));
            v.z = w4.z - LR_ * t;
            t = cm * mu4.w + ca * a4.w;
            d = w4.w - wlag4.w;  t += COST_ * d * rsqrtf(fmaf(d, d, 1e-10f));
            d = wnext4.w - w4.w; t -= fnext * COST_ * d * rsqrtf(fmaf(d, d, 1e-10f));
            v.w = w4.w - LR_ * t;
        }
        if (!vlane) v = make_float4(-1e30f, -1e30f, -1e30f, -1e30f);

        // --- exact simplex projection (Michelot; == sort-based projection) ---
        float s0 = red1(vlane ? (v.x + v.y + v.z + v.w) : 0.0f);
        float kk    = 100.0f;
        float theta = (s0 - 1.0f) * 0.01f;
#pragma unroll 1
        for (int pass = 0; pass < 50; pass++) {
            float bs = 0.0f, bk = 0.0f;
            if (v.x > theta) { bs += v.x; bk += 1.0f; }
            if (v.y > theta) { bs += v.y; bk += 1.0f; }
            if (v.z > theta) { bs += v.z; bk += 1.0f; }
            if (v.w > theta) { bs += v.w; bk += 1.0f; }
            red2(bs, bk);
            if (bk == kk) break;
            kk = bk;
            theta = (bs - 1.0f) / bk;
        }
        w4.x = fmaxf(v.x - theta, 0.0f);
        w4.y = fmaxf(v.y - theta, 0.0f);
        w4.z = fmaxf(v.z - theta, 0.0f);
        w4.w = fmaxf(v.w - theta, 0.0f);

        // --- publish new w; CTA-local sync; signal neighbors ---
        if (half == 0 && vlane)
            *(float4*)(wbuf + ((cur ^ 1) * HPC + head) * 128 + 4 * lane) = w4;
        __syncthreads();
        if (tid == 0 && it + 1 < ITERS) {
            const int bp = cur ^ 1;     // buffer just published
            if (has_lo) mbar_arrive_remote(bp ? arr_lo1 : arr_lo0);
            if (has_hi) mbar_arrive_remote(bp ? arr_hi1 : arr_hi0);
        }
    }

    if (half == 0 && vlane)
        *(float4*)(out + (size_t)bh * Nn + 4 * lane) = w4;

    // Keep cluster SMEM alive until all CTAs are done with DSMEM traffic.
    CLUSTER_SYNC_();
}

// ---------------------------------------------------------------------------
// Launch
// ---------------------------------------------------------------------------
extern "C" void kernel_launch(void* const* d_in, const int* in_sizes, int n_in,
                              void* d_out, int out_size) {
    const float *mu = nullptr, *L = nullptr, *wprev = nullptr, *lim = nullptr;
    for (int i = 0; i < n_in; i++) {
        switch (in_sizes[i]) {
            case Bn * Hn * Nn:       mu    = (const float*)d_in[i]; break;
            case Bn * Hn * Nn * Nn:  L     = (const float*)d_in[i]; break;
            case Bn * Nn:            wprev = (const float*)d_in[i]; break;
            case Bn:                 lim   = (const float*)d_in[i]; break;
            default: break;
        }
    }
    float* out = (float*)d_out;

    cudaFuncSetAttribute(solve_kernel, cudaFuncAttributeMaxDynamicSharedMemorySize, SMEM_BYTES);

    precompute_G<<<Bn * Hn, 256>>>(L);
    solve_kernel<<<Bn * CL, NT, SMEM_BYTES>>>(mu, wprev, lim, out);
}

// round 16
// speedup vs baseline: 1.5065x; 1.0130x over previous
#include <cuda_runtime.h>
#include <cuda_fp16.h>
#include <cstdint>

// ---------------- problem constants ----------------
#define Bn    128
#define Hn    12
#define Nn    100
#define NPH   104            // padded G row pitch in halfs (208B rows, 16B aligned)
#define HPC   4              // heads per CTA
#define CL    3              // CTAs per cluster (HPC*CL == Hn)
#define WPH   2              // warps per head
#define NW    (HPC*WPH)      // 8 warps per CTA
#define NT    (NW*32)        // 256 threads
#define ITERS 500

#define GAMMA_ 5.0f
#define COST_  1e-3f
#define KAPPA_ 2.0627128075074256f
#define PEN_   100.0f
#define LR_    0.01f

// SMEM layout (bytes)
#define G_BYTES    (HPC*Nn*NPH*2)              // 83200
#define WBUF_BYTE  G_BYTES                     // fp32 w: [2][HPC][128] = 4096 B
#define PA_BYTE    (WBUF_BYTE + 2*HPC*128*4)   // partial-a: [NW][128] f32
#define MB_BYTE    (PA_BYTE + NW*128*4)        // 2 mbarriers (16 B)
#define SMEM_BYTES (MB_BYTE + 16)              // 91408 B -> 2 CTAs/SM

// Scratch for G = L L^T per (b,h) in fp16 (~32 MB)
__device__ __half g_G[(size_t)Bn * Hn * Nn * NPH];

// ---------------------------------------------------------------------------
// Precompute G[b,h] = L L^T (fp32 accumulate, fp16 store)
// ---------------------------------------------------------------------------
__global__ __launch_bounds__(256) void precompute_G(const float* __restrict__ L) {
    __shared__ __align__(16) float Ls[Nn * Nn];
    const int bh = blockIdx.x;
    const float4* src = (const float4*)(L + (size_t)bh * Nn * Nn);
    float4* d4 = (float4*)Ls;
    for (int i = threadIdx.x; i < Nn * Nn / 4; i += blockDim.x) d4[i] = src[i];
    __syncthreads();
    __half* outp = g_G + (size_t)bh * Nn * NPH;
    for (int idx = threadIdx.x; idx < Nn * NPH; idx += blockDim.x) {
        const int n = idx / NPH;
        const int j = idx - n * NPH;
        float r = 0.0f;
        if (j < Nn) {
            const float4* ra = (const float4*)(Ls + n * Nn);
            const float4* rb = (const float4*)(Ls + j * Nn);
            float a0 = 0.f, a1 = 0.f, a2 = 0.f, a3 = 0.f;
#pragma unroll
            for (int m = 0; m < Nn / 4; m++) {
                float4 x = ra[m], y = rb[m];
                a0 = fmaf(x.x, y.x, a0);
                a1 = fmaf(x.y, y.y, a1);
                a2 = fmaf(x.z, y.z, a2);
                a3 = fmaf(x.w, y.w, a3);
            }
            r = (a0 + a1) + (a2 + a3);
        }
        outp[idx] = __float2half_rn(r);
    }
}

// ---------------------------------------------------------------------------
// Helpers
// ---------------------------------------------------------------------------
__device__ __forceinline__ float red1(float x) {
#pragma unroll
    for (int o = 16; o; o >>= 1) x += __shfl_xor_sync(0xffffffffu, x, o);
    return x;
}

__device__ __forceinline__ void red2(float& x, float& y) {
#pragma unroll
    for (int o = 16; o; o >>= 1) {
        x += __shfl_xor_sync(0xffffffffu, x, o);
        y += __shfl_xor_sync(0xffffffffu, y, o);
    }
}

__device__ __forceinline__ void red4(float& x, float& y, float& z, float& w) {
#pragma unroll
    for (int o = 16; o; o >>= 1) {
        x += __shfl_xor_sync(0xffffffffu, x, o);
        y += __shfl_xor_sync(0xffffffffu, y, o);
        z += __shfl_xor_sync(0xffffffffu, z, o);
        w += __shfl_xor_sync(0xffffffffu, w, o);
    }
}

#define CLUSTER_SYNC_() \
    asm volatile("barrier.cluster.arrive.aligned;\n\tbarrier.cluster.wait.aligned;" ::: "memory")

#define PAIR_BAR_(id) \
    asm volatile("bar.sync %0, 64;" :: "r"(id) : "memory")

// Wait on local mbarrier with given phase parity, acquire at cluster scope.
__device__ __forceinline__ void mbar_wait_cluster(uint32_t addr, uint32_t par) {
    asm volatile(
        "{\n\t.reg .pred P;\n\t"
        "WAITL_%=:\n\t"
        "mbarrier.try_wait.parity.acquire.cluster.shared::cta.b64 P, [%0], %1, 0x989680;\n\t"
        "@P bra.uni WD_%=;\n\t"
        "bra.uni WAITL_%=;\n\t"
        "WD_%=:\n\t}"
        :: "r"(addr), "r"(par) : "memory");
}

// Arrive on a (mapa-resolved) remote CTA mbarrier, release at cluster scope.
__device__ __forceinline__ void mbar_arrive_remote(uint32_t remote_addr) {
    asm volatile(
        "mbarrier.arrive.release.cluster.shared::cluster.b64 _, [%0];"
        :: "r"(remote_addr) : "memory");
}

// ---------------------------------------------------------------------------
// Solver: cluster of 3 CTAs per batch; CTA rank r owns heads 4r..4r+3,
// two warps per head. G fp16 in SMEM; fp32 math. Neighbor mbarrier
// handshakes for cross-CTA sync. Single fused 4-wide reduction tree.
// ---------------------------------------------------------------------------
__global__ __cluster_dims__(CL, 1, 1) __launch_bounds__(NT, 2)
void solve_kernel(const float* __restrict__ mu, const float* __restrict__ wprev,
                  const float* __restrict__ lim, float* __restrict__ out)
{
    extern __shared__ __align__(16) char smraw[];
    __half* Gs  = (__half*)smraw;                 // [HPC][Nn][NPH] fp16
    float* wbuf = (float*)(smraw + WBUF_BYTE);    // [2][HPC][128] fp32
    float* pa   = (float*)(smraw + PA_BYTE);      // [NW][128] partial-a

    const int tid  = threadIdx.x;
    const int lane = tid & 31;
    const int warp = tid >> 5;            // 0..7
    const int head = warp & (HPC - 1);    // head within CTA
    const int half = warp >> 2;           // 0: j in [0,52), 1: j in [52,100)
    uint32_t rank;
    asm("mov.u32 %0, %%cluster_ctarank;" : "=r"(rank));
    const int  b   = blockIdx.x / CL;
    const int  h   = HPC * (int)rank + head;
    const int  bh  = b * Hn + h;
    const bool vlane = (lane < 25);       // 25 lanes x 4 elems = 100
    const int  lv  = vlane ? lane : 24;   // clamped lane for safe addresses

    const uint32_t smem_u32 = (uint32_t)__cvta_generic_to_shared(smraw);
    const uint32_t mb0 = smem_u32 + MB_BYTE;      // full[0]
    const uint32_t mb1 = mb0 + 8;                 // full[1]
    const bool has_lo = (rank > 0);
    const bool has_hi = (rank + 1 < CL);

    // Load this CTA's 4 fp16 G matrices into SMEM
    {
        const uint4* s4 = (const uint4*)(g_G + (size_t)(b * Hn + HPC * (int)rank) * Nn * NPH);
        uint4* d4 = (uint4*)Gs;
        const int n4 = G_BYTES / 16;
        for (int i = tid; i < n4; i += NT) d4[i] = s4[i];
    }
    // Init both w buffers, zero pads
    for (int i = tid; i < 2 * HPC * 128; i += NT) {
        int e = i & 127;
        wbuf[i] = (e < Nn) ? wprev[(size_t)b * Nn + e] : 0.0f;
    }
    // Init neighbor-handshake mbarriers (count = number of neighbors)
    if (tid == 0) {
        const uint32_t n_nb = (uint32_t)((has_lo ? 1 : 0) + (has_hi ? 1 : 0));
        asm volatile("mbarrier.init.shared.b64 [%0], %1;" :: "r"(mb0), "r"(n_nb) : "memory");
        asm volatile("mbarrier.init.shared.b64 [%0], %1;" :: "r"(mb1), "r"(n_nb) : "memory");
    }

    // Per-lane registers
    float4 mu4, w4, wlag0;
    {
        const float4* mp = (const float4*)(mu + (size_t)bh * Nn);
        const float4* pp = (const float4*)(wprev + (size_t)b * Nn);
        float4 m = mp[lv], p = pp[lv];
        if (!vlane) { m = make_float4(0, 0, 0, 0); p = make_float4(0, 0, 0, 0); }
        mu4 = m; w4 = p; wlag0 = p;       // constant lag for h==0
    }
    // Warp-uniform sum of mu (used by the algebraic theta init)
    const float SUM_MU = red1(vlane ? (mu4.x + mu4.y + mu4.z + mu4.w) : 0.0f);

    const float limb    = lim[b];
    const bool  h_first = (h == 0);
    const bool  h_last  = (h == Hn - 1);
    const float fnext   = h_last ? 0.0f : 1.0f;
    // This warp performs cross-CTA reads -> must wait on the handshake
    const bool remote_rd = (head == 0 && has_lo) || (head == HPC - 1 && has_hi);

    // DSMEM addresses for boundary-head neighbor reads (per buffer) and
    // for remote arrivals on neighbors' full[] barriers.
    uint32_t ra_lag[2], ra_next[2];
    uint32_t arr_lo0 = 0, arr_lo1 = 0, arr_hi0 = 0, arr_hi1 = 0;
    {
        uint32_t wbase = (uint32_t)__cvta_generic_to_shared(wbuf);
        uint32_t rlo = has_lo ? (rank - 1) : 0u;
        uint32_t rhi = has_hi ? (rank + 1) : rank;
#pragma unroll
        for (int bu = 0; bu < 2; bu++) {
            uint32_t off_lag  = wbase + (uint32_t)(((bu * HPC + (HPC - 1)) * 128 + 4 * lv) * 4);
            uint32_t off_next = wbase + (uint32_t)(((bu * HPC + 0) * 128 + 4 * lv) * 4);
            asm("mapa.shared::cluster.u32 %0, %1, %2;" : "=r"(ra_lag[bu])  : "r"(off_lag),  "r"(rlo));
            asm("mapa.shared::cluster.u32 %0, %1, %2;" : "=r"(ra_next[bu]) : "r"(off_next), "r"(rhi));
        }
        asm("mapa.shared::cluster.u32 %0, %1, %2;" : "=r"(arr_lo0) : "r"(mb0), "r"(rlo));
        asm("mapa.shared::cluster.u32 %0, %1, %2;" : "=r"(arr_lo1) : "r"(mb1), "r"(rlo));
        asm("mapa.shared::cluster.u32 %0, %1, %2;" : "=r"(arr_hi0) : "r"(mb0), "r"(rhi));
        asm("mapa.shared::cluster.u32 %0, %1, %2;" : "=r"(arr_hi1) : "r"(mb1), "r"(rhi));
    }

    CLUSTER_SYNC_();   // publish G + initial w + mbarrier init to whole cluster

    const __half* Gh = Gs + head * (Nn * NPH) + 4 * lv;   // lane's 4-elem slab
    float* paw       = pa + warp * 128;                   // own partial slot
    const float* pao = pa + (warp ^ 4) * 128 + 4 * lv;    // pair's partial slot
    const int j0 = half ? 52 : 0;
    const int j1 = half ? 100 : 52;
    const int barid = 1 + head;

    for (int it = 0; it < ITERS; it++) {
        const int cur = it & 1;
        const float* wc = wbuf + (cur * HPC + head) * 128;   // head's current w

        // --- handshake: remote-reading warps wait for neighbor publish ---
        if (it > 0 && remote_rd) {
            mbar_wait_cluster(cur ? mb1 : mb0, (uint32_t)(((it - 1) >> 1) & 1));
        }

        // --- neighbor reads (issued early; latency hidden by matvec) ---
        float4 wlag4, wnext4;
        if (h_first) {
            wlag4 = wlag0;
        } else if (head > 0) {
            wlag4 = *(const float4*)(wbuf + (cur * HPC + head - 1) * 128 + 4 * lv);
        } else {
            asm volatile("ld.shared::cluster.v4.f32 {%0,%1,%2,%3}, [%4];"
                         : "=f"(wlag4.x), "=f"(wlag4.y), "=f"(wlag4.z), "=f"(wlag4.w)
                         : "r"(ra_lag[cur]));
        }
        if (h_last) {
            wnext4 = make_float4(0, 0, 0, 0);
        } else if (head < HPC - 1) {
            wnext4 = *(const float4*)(wbuf + (cur * HPC + head + 1) * 128 + 4 * lv);
        } else {
            asm volatile("ld.shared::cluster.v4.f32 {%0,%1,%2,%3}, [%4];"
                         : "=f"(wnext4.x), "=f"(wnext4.y), "=f"(wnext4.z), "=f"(wnext4.w)
                         : "r"(ra_next[cur]));
        }

        // --- partial a = G w over this warp's j-range (fp16 G, fp32 math) ---
        float4 aA = make_float4(0, 0, 0, 0);
        float4 aB = make_float4(0, 0, 0, 0);
#define ROWF4(J) ({                                                            \
            uint2 _u = *(const uint2*)(Gh + (size_t)(J) * NPH);                \
            __half2 _p, _q;                                                    \
            *reinterpret_cast<uint32_t*>(&_p) = _u.x;                          \
            *reinterpret_cast<uint32_t*>(&_q) = _u.y;                          \
            float2 _a = __half22float2(_p);                                    \
            float2 _b = __half22float2(_q);                                    \
            make_float4(_a.x, _a.y, _b.x, _b.y); })
#define BLK4(J, ACC) do {                                                      \
            float4 wv = *(const float4*)(wc + (J));                            \
            float4 g0 = ROWF4((J) + 0);                                        \
            float4 g1 = ROWF4((J) + 1);                                        \
            float4 g2 = ROWF4((J) + 2);                                        \
            float4 g3 = ROWF4((J) + 3);                                        \
            ACC.x = fmaf(g0.x, wv.x, ACC.x); ACC.y = fmaf(g0.y, wv.x, ACC.y);  \
            ACC.z = fmaf(g0.z, wv.x, ACC.z); ACC.w = fmaf(g0.w, wv.x, ACC.w);  \
            ACC.x = fmaf(g1.x, wv.y, ACC.x); ACC.y = fmaf(g1.y, wv.y, ACC.y);  \
            ACC.z = fmaf(g1.z, wv.y, ACC.z); ACC.w = fmaf(g1.w, wv.y, ACC.w);  \
            ACC.x = fmaf(g2.x, wv.z, ACC.x); ACC.y = fmaf(g2.y, wv.z, ACC.y);  \
            ACC.z = fmaf(g2.z, wv.z, ACC.z); ACC.w = fmaf(g2.w, wv.z, ACC.w);  \
            ACC.x = fmaf(g3.x, wv.w, ACC.x); ACC.y = fmaf(g3.y, wv.w, ACC.y);  \
            ACC.z = fmaf(g3.z, wv.w, ACC.z); ACC.w = fmaf(g3.w, wv.w, ACC.w);  \
        } while (0)
        int j = j0;
#pragma unroll 3
        for (; j + 8 <= j1; j += 8) {
            BLK4(j, aA);
            BLK4(j + 4, aB);
        }
        if (j < j1) BLK4(j, aA);
#undef BLK4
#undef ROWF4
        aA.x += aB.x; aA.y += aB.y; aA.z += aB.z; aA.w += aB.w;

        // --- turnover (cost) terms; overlap with pair-combine wait ---
        float4 cst;
        {
            float d;
            d = w4.x - wlag4.x;  cst.x = COST_ * d * rsqrtf(fmaf(d, d, 1e-10f));
            d = wnext4.x - w4.x; cst.x -= fnext * COST_ * d * rsqrtf(fmaf(d, d, 1e-10f));
            d = w4.y - wlag4.y;  cst.y = COST_ * d * rsqrtf(fmaf(d, d, 1e-10f));
            d = wnext4.y - w4.y; cst.y -= fnext * COST_ * d * rsqrtf(fmaf(d, d, 1e-10f));
            d = w4.z - wlag4.z;  cst.z = COST_ * d * rsqrtf(fmaf(d, d, 1e-10f));
            d = wnext4.z - w4.z; cst.z -= fnext * COST_ * d * rsqrtf(fmaf(d, d, 1e-10f));
            d = w4.w - wlag4.w;  cst.w = COST_ * d * rsqrtf(fmaf(d, d, 1e-10f));
            d = wnext4.w - w4.w; cst.w -= fnext * COST_ * d * rsqrtf(fmaf(d, d, 1e-10f));
        }

        // --- combine halves through SMEM scratch (per-head named barrier) ---
        if (vlane) *(float4*)(paw + 4 * lane) = aA;
        PAIR_BAR_(barid);
        float4 oth = *(const float4*)pao;
        float4 a4;
        a4.x = aA.x + oth.x; a4.y = aA.y + oth.y;
        a4.z = aA.z + oth.z; a4.w = aA.w + oth.w;

        // --- fused reductions: mu.w, w.Gw, sum(a), sum(cost) ---
        float p0 = mu4.x * w4.x + mu4.y * w4.y + mu4.z * w4.z + mu4.w * w4.w;
        float p1 = w4.x * a4.x + w4.y * a4.y + w4.z * a4.z + w4.w * a4.w;
        float p2 = vlane ? (a4.x + a4.y + a4.z + a4.w) : 0.0f;
        float p3 = vlane ? (cst.x + cst.y + cst.z + cst.w) : 0.0f;
        red4(p0, p1, p2, p3);
        const float s2      = p1 + 1e-12f;
        const float inv_sig = rsqrtf(s2);
        const float sigma   = s2 * inv_sig;
        const float zv      = KAPPA_ * sigma - p0 - limb;
        const float pen     = (zv > 0.0f) ? PEN_ : 0.0f;
        const float ca      = 2.0f * GAMMA_ + pen * KAPPA_ * inv_sig;
        const float cm      = -(1.0f + pen);

        // --- gradient + step: v = w - LR*(cm*mu + ca*a + cost) ---
        float4 v;
        v.x = w4.x - LR_ * (cm * mu4.x + ca * a4.x + cst.x);
        v.y = w4.y - LR_ * (cm * mu4.y + ca * a4.y + cst.y);
        v.z = w4.z - LR_ * (cm * mu4.z + ca * a4.z + cst.z);
        v.w = w4.w - LR_ * (cm * mu4.w + ca * a4.w + cst.w);
        if (!vlane) v = make_float4(-1e30f, -1e30f, -1e30f, -1e30f);

        // Algebraic Sum(v): Sum(w)=1 (fresh projection), so
        // Sum(v) = 1 - LR*(cm*SUM_MU + ca*Sum(a) + Sum(cost)).
        const float s0 = 1.0f - LR_ * (cm * SUM_MU + ca * p2 + p3);

        // --- exact simplex projection (Michelot; == sort-based projection) ---
        float kk    = 100.0f;
        float theta = (s0 - 1.0f) * 0.01f;
#pragma unroll 1
        for (int pass = 0; pass < 50; pass++) {
            float bs = 0.0f, bk = 0.0f;
            if (v.x > theta) { bs += v.x; bk += 1.0f; }
            if (v.y > theta) { bs += v.y; bk += 1.0f; }
            if (v.z > theta) { bs += v.z; bk += 1.0f; }
            if (v.w > theta) { bs += v.w; bk += 1.0f; }
            red2(bs, bk);
            if (bk == kk) break;
            kk = bk;
            theta = (bs - 1.0f) / bk;
        }
        w4.x = fmaxf(v.x - theta, 0.0f);
        w4.y = fmaxf(v.y - theta, 0.0f);
        w4.z = fmaxf(v.z - theta, 0.0f);
        w4.w = fmaxf(v.w - theta, 0.0f);

        // --- publish new w; CTA-local sync; signal neighbors ---
        if (half == 0 && vlane)
            *(float4*)(wbuf + ((cur ^ 1) * HPC + head) * 128 + 4 * lane) = w4;
        __syncthreads();
        if (tid == 0 && it + 1 < ITERS) {
            const int bp = cur ^ 1;     // buffer just published
            if (has_lo) mbar_arrive_remote(bp ? arr_lo1 : arr_lo0);
            if (has_hi) mbar_arrive_remote(bp ? arr_hi1 : arr_hi0);
        }
    }

    if (half == 0 && vlane)
        *(float4*)(out + (size_t)bh * Nn + 4 * lane) = w4;

    // Keep cluster SMEM alive until all CTAs are done with DSMEM traffic.
    CLUSTER_SYNC_();
}

// ---------------------------------------------------------------------------
// Launch
// ---------------------------------------------------------------------------
extern "C" void kernel_launch(void* const* d_in, const int* in_sizes, int n_in,
                              void* d_out, int out_size) {
    const float *mu = nullptr, *L = nullptr, *wprev = nullptr, *lim = nullptr;
    for (int i = 0; i < n_in; i++) {
        switch (in_sizes[i]) {
            case Bn * Hn * Nn:       mu    = (const float*)d_in[i]; break;
            case Bn * Hn * Nn * Nn:  L     = (const float*)d_in[i]; break;
            case Bn * Nn:            wprev = (const float*)d_in[i]; break;
            case Bn:                 lim   = (const float*)d_in[i]; break;
            default: break;
        }
    }
    float* out = (float*)d_out;

    cudaFuncSetAttribute(solve_kernel, cudaFuncAttributeMaxDynamicSharedMemorySize, SMEM_BYTES);

    precompute_G<<<Bn * Hn, 256>>>(L);
    solve_kernel<<<Bn * CL, NT, SMEM_BYTES>>>(mu, wprev, lim, out);
}